// round 7
// baseline (speedup 1.0000x reference)
#include <cuda_runtime.h>
#include <cstdint>

// SlidingKVQCache on GB300 — R7: copy-engine experiment.
//
// out[c][i] = cache[c][i+32] for all i in [0, CACHE4-32), EXCEPT the 32-float4
// tail of each 65536-float4 (b,h) slab, which must hold the new token. So:
//   1) 3x cudaMemcpyAsync D2D: out[c][0..CACHE4-32) <- cache[c][32..CACHE4)
//      (writes garbage at the 127 interior slab tails — fixed up next)
//   2) fixup kernel: out[c][bh*65536 + 65504 + j] = tok[c][bh*32 + j]
//      for bh in [0,128), j in [0,32)  — 12288 float4 total, negligible.

static constexpr unsigned CACHE4 = 1u << 23;            // 8388608 float4 per cache
static constexpr unsigned SLAB4  = 65536u;
static constexpr unsigned TAIL4  = SLAB4 - 32u;          // 65504
static constexpr size_t  COPY_BYTES = (size_t)(CACHE4 - 32u) * sizeof(float4);

// 3 caches * 128 slabs * 32 float4 = 12288 fixup elements
static constexpr int FIX_TOTAL = 3 * 128 * 32;

__global__ void token_fixup_kernel(
    const float4* __restrict__ kt,
    const float4* __restrict__ vt,
    const float4* __restrict__ qt,
    float4* __restrict__ out)
{
    int t = blockIdx.x * blockDim.x + threadIdx.x;   // [0, 12288)
    if (t >= FIX_TOTAL) return;
    int c  = t >> 12;                 // t / 4096  (128*32 per cache)
    int r  = t & 4095;
    int bh = r >> 5;                  // slab index
    int j  = r & 31;                  // float4 within token row

    const float4* __restrict__ tok = (c == 0) ? kt : (c == 1) ? vt : qt;
    out[(size_t)c * CACHE4 + (size_t)bh * SLAB4 + TAIL4 + j] = tok[(bh << 5) + j];
}

extern "C" void kernel_launch(void* const* d_in, const int* in_sizes, int n_in,
                              void* d_out, int out_size)
{
    const float4* kc = (const float4*)d_in[0];
    const float4* vc = (const float4*)d_in[1];
    const float4* qc = (const float4*)d_in[2];
    const float4* kt = (const float4*)d_in[3];
    const float4* vt = (const float4*)d_in[4];
    const float4* qt = (const float4*)d_in[5];
    float4* out = (float4*)d_out;

    // Bulk shifted copies (device-to-device, async, capture-legal)
    cudaMemcpyAsync(out,                kc + 32, COPY_BYTES, cudaMemcpyDeviceToDevice, 0);
    cudaMemcpyAsync(out + CACHE4,       vc + 32, COPY_BYTES, cudaMemcpyDeviceToDevice, 0);
    cudaMemcpyAsync(out + 2 * CACHE4,   qc + 32, COPY_BYTES, cudaMemcpyDeviceToDevice, 0);

    // Overwrite slab tails with the new tokens
    token_fixup_kernel<<<(FIX_TOTAL + 255) / 256, 256>>>(kt, vt, qt, out);
}

// round 8
// speedup vs baseline: 2.2980x; 2.2980x over previous
#include <cuda_runtime.h>
#include <cstdint>

// SlidingKVQCache on GB300 — R8: R2 winner body, cache-interleaved scheduling.
//
// Flat per-cache view (float4 units): slab = 2048*32 = 65536 = 2^16 per (b,h).
//   out[i] = cache[i + 32]                         if (i & 65535) < 65504
//   out[i] = tok[(i>>16)*32 + ((i&65535)-65504)]   otherwise (last token row)
//
// 1D grid of 24576 blocks; c = blockIdx.x % 3 so consecutive blocks hit
// different caches -> 3 read + 3 write streams live concurrently (bank-group
// parallelism at the HBM controller). Body: U=4 front-batched LDG.128 + STG.128.

static constexpr unsigned SLABMASK = 65535u;
static constexpr unsigned TAIL4    = 65504u;
static constexpr unsigned CACHE4   = 1u << 23;          // 8388608 float4 per cache

static constexpr int THREADS = 256;
static constexpr int U = 4;                             // float4 per thread
static constexpr unsigned PER_BLOCK = THREADS * U;      // 1024
static constexpr unsigned BLOCKS_PER_CACHE = CACHE4 / PER_BLOCK;  // 8192

__global__ __launch_bounds__(THREADS, 8)
void sliding_cache_interleave_kernel(
    const float4* __restrict__ kc,
    const float4* __restrict__ vc,
    const float4* __restrict__ qc,
    const float4* __restrict__ kt,
    const float4* __restrict__ vt,
    const float4* __restrict__ qt,
    float4* __restrict__ out)
{
    const unsigned bx = blockIdx.x;
    const unsigned chunk = bx / 3u;          // [0, 8192)
    const unsigned c     = bx - chunk * 3u;  // cache id, interleaved fastest

    const float4* __restrict__ cache = (c == 0) ? kc : (c == 1) ? vc : qc;
    const float4* __restrict__ tok   = (c == 0) ? kt : (c == 1) ? vt : qt;
    float4* __restrict__ ob = out + (size_t)c * CACHE4;

    const unsigned base = chunk * PER_BLOCK + threadIdx.x;

    unsigned idx[U];
    const float4* __restrict__ src[U];

    #pragma unroll
    for (int k = 0; k < U; k++) {
        idx[k] = base + (unsigned)k * THREADS;
        unsigned pos = idx[k] & SLABMASK;
        src[k] = (pos < TAIL4)
               ? cache + idx[k] + 32
               : tok + ((idx[k] >> 16) << 5) + (pos - TAIL4);
    }

    float4 v[U];
    #pragma unroll
    for (int k = 0; k < U; k++) v[k] = *src[k];   // front-batched LDG.128 x4

    #pragma unroll
    for (int k = 0; k < U; k++) ob[idx[k]] = v[k];
}

extern "C" void kernel_launch(void* const* d_in, const int* in_sizes, int n_in,
                              void* d_out, int out_size)
{
    const float4* kc = (const float4*)d_in[0];
    const float4* vc = (const float4*)d_in[1];
    const float4* qc = (const float4*)d_in[2];
    const float4* kt = (const float4*)d_in[3];
    const float4* vt = (const float4*)d_in[4];
    const float4* qt = (const float4*)d_in[5];
    float4* out = (float4*)d_out;

    sliding_cache_interleave_kernel<<<BLOCKS_PER_CACHE * 3, THREADS>>>(
        kc, vc, qc, kt, vt, qt, out);
}